// round 1
// baseline (speedup 1.0000x reference)
#include <cuda_runtime.h>

// ---------------- problem constants ----------------
#define NN 50000
#define EE 800000
#define HH 64
#define RR 8
#define LL 3
#define LN_EPS 1e-5f
#define NEG_SLOPE 0.2f

// ---------------- device scratch (allocation-free rule: __device__ globals) ----
__device__ float g_h[2 * NN * HH];        // ping-pong node features
__device__ float g_hWr[(size_t)NN * 512]; // h @ W_rel^T  [N][R*H]
__device__ float g_gate[(size_t)NN * 512];// raw gate pre-activation [N][R*H]
__device__ float g_agg[(size_t)NN * 512]; // scatter accumulator [N][R*H]
__device__ float g_ap[NN * 16];           // attention projections [N][16] (src:0..7, dst:8..15)
__device__ float g_sc[EE];                // per-edge scores
__device__ float g_ex[EE];                // per-edge exp(score - max)
__device__ unsigned g_menc[RR];           // per-type max (order-encoded float)
__device__ float g_denom[RR];             // per-type softmax denominator

// order-preserving float<->uint encoding for atomicMax on floats
__device__ __forceinline__ unsigned fenc(float f) {
    unsigned u = __float_as_uint(f);
    return (u & 0x80000000u) ? ~u : (u | 0x80000000u);
}
__device__ __forceinline__ float fdec(unsigned e) {
    unsigned u = (e & 0x80000000u) ? (e ^ 0x80000000u) : ~e;
    return __uint_as_float(u);
}

// ---------------- generic K=64 SGEMM: C[M,ncols] = act(A[M,64] @ B[ncols,64]^T + bias) ----
// BM=128, BN=64, full K slab in smem. 8x8 micro-tiles, packed fma.rn.f32x2.
#define GEMM_SMEM ((64 * 129 + 64 * 66) * 4)

__global__ __launch_bounds__(128)
void gemm64k(const float* __restrict__ A, const float* __restrict__ B,
             const float* __restrict__ bias, float* __restrict__ C,
             int M, int ncols, int act)
{
    extern __shared__ float smem[];
    float (*As)[129] = reinterpret_cast<float (*)[129]>(smem);            // As[k][row]
    float (*Bs)[66]  = reinterpret_cast<float (*)[66]>(smem + 64 * 129);  // Bs[k][col]

    const int tid = threadIdx.x;
    const int rowBase = blockIdx.x * 128;
    const int colBase = blockIdx.y * 64;

    // stage A tile (128 rows x 64 k), transposed into smem
    #pragma unroll
    for (int i = 0; i < 16; i++) {
        int f = tid + i * 128;         // float4 index
        int r = f >> 4;                // 16 float4 per row
        int kq = (f & 15) << 2;
        int gr = rowBase + r;
        float4 v = make_float4(0.f, 0.f, 0.f, 0.f);
        if (gr < M) v = *reinterpret_cast<const float4*>(A + (size_t)gr * 64 + kq);
        As[kq + 0][r] = v.x; As[kq + 1][r] = v.y; As[kq + 2][r] = v.z; As[kq + 3][r] = v.w;
    }
    // stage B tile (64 cols x 64 k), transposed into smem
    #pragma unroll
    for (int i = 0; i < 8; i++) {
        int f = tid + i * 128;
        int j = f >> 4;
        int kq = (f & 15) << 2;
        float4 v = *reinterpret_cast<const float4*>(B + (size_t)(colBase + j) * 64 + kq);
        Bs[kq + 0][j] = v.x; Bs[kq + 1][j] = v.y; Bs[kq + 2][j] = v.z; Bs[kq + 3][j] = v.w;
    }
    __syncthreads();

    const int tx = tid & 7;    // col group: cols tx*8 .. tx*8+7
    const int ty = tid >> 3;   // row group: rows ty*8 .. ty*8+7

    unsigned long long acc[8][4];
    #pragma unroll
    for (int i = 0; i < 8; i++)
        #pragma unroll
        for (int j = 0; j < 4; j++) acc[i][j] = 0ULL;

    #pragma unroll
    for (int k = 0; k < 64; k++) {
        float a[8];
        #pragma unroll
        for (int i = 0; i < 8; i++) a[i] = As[k][ty * 8 + i];
        unsigned long long b2[4];
        const unsigned long long* bp =
            reinterpret_cast<const unsigned long long*>(&Bs[k][tx * 8]);
        #pragma unroll
        for (int j = 0; j < 4; j++) b2[j] = bp[j];
        #pragma unroll
        for (int i = 0; i < 8; i++) {
            unsigned long long a2;
            asm("mov.b64 %0, {%1, %1};" : "=l"(a2) : "f"(a[i]));
            #pragma unroll
            for (int j = 0; j < 4; j++)
                asm("fma.rn.f32x2 %0, %1, %2, %0;" : "+l"(acc[i][j]) : "l"(a2), "l"(b2[j]));
        }
    }

    #pragma unroll
    for (int i = 0; i < 8; i++) {
        int gr = rowBase + ty * 8 + i;
        if (gr >= M) continue;
        #pragma unroll
        for (int j = 0; j < 4; j++) {
            float lo, hi;
            asm("mov.b64 {%0, %1}, %2;" : "=f"(lo), "=f"(hi) : "l"(acc[i][j]));
            int col = colBase + tx * 8 + 2 * j;
            if (bias) { lo += bias[col]; hi += bias[col + 1]; }
            if (act == 1) { lo = fmaxf(lo, 0.f); hi = fmaxf(hi, 0.f); }
            *reinterpret_cast<float2*>(C + (size_t)gr * ncols + col) = make_float2(lo, hi);
        }
    }
}

// ---------------- attention projections: ap[n][r] = h[n]·Wa_src[r], ap[n][8+r] = h[n]·Wa_dst[r]
__global__ __launch_bounds__(256)
void attproj_k(const float* __restrict__ h, const float* __restrict__ W_att)
{
    __shared__ float hs[16][65];
    __shared__ float ws[16][65];
    int tid = threadIdx.x;
    int nodeBase = blockIdx.x * 16;
    for (int i = tid; i < 16 * 64; i += 256) {
        int o = i >> 6, c = i & 63;
        ws[o][c] = W_att[(o & 7) * 128 + ((o >> 3) << 6) + c];
        int n = nodeBase + o;
        hs[o][c] = (n < NN) ? h[n * 64 + c] : 0.f;
    }
    __syncthreads();
    int nd = tid >> 4, o = tid & 15;
    float s = 0.f;
    #pragma unroll
    for (int c = 0; c < 64; c++) s += hs[nd][c] * ws[o][c];
    int n = nodeBase + nd;
    if (n < NN) g_ap[n * 16 + o] = s;
    // piggyback per-layer softmax-stat reset (safe: consumed only by later launches)
    if (blockIdx.x == 0 && tid < RR) { g_menc[tid] = 0u; g_denom[tid] = 0.f; }
}

// ---------------- per-edge scores + per-type max ----------------
__global__ __launch_bounds__(256)
void scores_k(const int* __restrict__ ei, const int* __restrict__ et,
              const float* __restrict__ b_att)
{
    __shared__ unsigned smax[RR];
    int tid = threadIdx.x;
    if (tid < RR) smax[tid] = 0u;
    __syncthreads();
    int e = blockIdx.x * 256 + tid;
    if (e < EE) {
        int t = et[e];
        int s = ei[e], d = ei[EE + e];
        float sc = g_ap[s * 16 + t] + g_ap[d * 16 + 8 + t] + b_att[t];
        sc = (sc > 0.f) ? sc : NEG_SLOPE * sc;
        g_sc[e] = sc;
        atomicMax(&smax[t], fenc(sc));
    }
    __syncthreads();
    if (tid < RR) atomicMax(&g_menc[tid], smax[tid]);
}

// ---------------- exp(score - max) + per-type denominator ----------------
__global__ __launch_bounds__(256)
void expk_k(const int* __restrict__ et)
{
    __shared__ float ssum[RR];
    int tid = threadIdx.x;
    if (tid < RR) ssum[tid] = 0.f;
    __syncthreads();
    int e = blockIdx.x * 256 + tid;
    if (e < EE) {
        int t = et[e];
        float m = fdec(g_menc[t]);
        float ex = __expf(g_sc[e] - m);
        g_ex[e] = ex;
        atomicAdd(&ssum[t], ex);
    }
    __syncthreads();
    if (tid < RR) atomicAdd(&g_denom[tid], ssum[tid]);
}

// ---------------- weighted message scatter: agg[dst,et,:] += att * hWr[src,et,:] ----
__global__ __launch_bounds__(256)
void scatter_k(const int* __restrict__ ei, const int* __restrict__ et)
{
    int t = blockIdx.x * 256 + threadIdx.x;  // EE*8 = 6.4M < 2^31
    int e = t >> 3;
    if (e >= EE) return;
    int g = t & 7;
    int ty = et[e];
    float att = g_ex[e] / g_denom[ty];
    const float4* p = reinterpret_cast<const float4*>(
        &g_hWr[(size_t)ei[e] * 512 + ty * 64 + g * 8]);
    float4 v1 = p[0], v2 = p[1];
    float* dp = &g_agg[(size_t)ei[EE + e] * 512 + ty * 64 + g * 8];
    atomicAdd(dp + 0, v1.x * att); atomicAdd(dp + 1, v1.y * att);
    atomicAdd(dp + 2, v1.z * att); atomicAdd(dp + 3, v1.w * att);
    atomicAdd(dp + 4, v2.x * att); atomicAdd(dp + 5, v2.y * att);
    atomicAdd(dp + 6, v2.z * att); atomicAdd(dp + 7, v2.w * att);
}

// ---------------- gate*agg mean + residual + LayerNorm + relu (warp per node) ----
// Also re-zeroes g_agg in place for the next layer / next replay.
__global__ __launch_bounds__(256)
void combine_k(const float* __restrict__ hin, float* __restrict__ hout,
               const float* __restrict__ b_gate,
               const float* __restrict__ gamma, const float* __restrict__ beta)
{
    int warp = threadIdx.x >> 5, lane = threadIdx.x & 31;
    int n = blockIdx.x * 8 + warp;
    if (n >= NN) return;
    size_t base = (size_t)n * 512;
    float acc1 = 0.f, acc2 = 0.f;
    #pragma unroll
    for (int r = 0; r < RR; r++) {
        int o1 = r * 64 + lane, o2 = o1 + 32;
        float p1 = g_gate[base + o1] + b_gate[o1];
        float p2 = g_gate[base + o2] + b_gate[o2];
        float s1 = 1.f / (1.f + __expf(-p1));
        float s2 = 1.f / (1.f + __expf(-p2));
        float a1 = g_agg[base + o1];
        float a2 = g_agg[base + o2];
        g_agg[base + o1] = 0.f;
        g_agg[base + o2] = 0.f;
        acc1 += s1 * a1;
        acc2 += s2 * a2;
    }
    float h1 = hin[n * 64 + lane] + acc1 * 0.125f;
    float h2 = hin[n * 64 + lane + 32] + acc2 * 0.125f;
    float s = h1 + h2;
    #pragma unroll
    for (int o = 16; o > 0; o >>= 1) s += __shfl_xor_sync(0xffffffffu, s, o);
    float mu = s * (1.f / 64.f);
    float d1 = h1 - mu, d2 = h2 - mu;
    float v = d1 * d1 + d2 * d2;
    #pragma unroll
    for (int o = 16; o > 0; o >>= 1) v += __shfl_xor_sync(0xffffffffu, v, o);
    float rs = rsqrtf(v * (1.f / 64.f) + LN_EPS);
    float o1 = d1 * rs * gamma[lane] + beta[lane];
    float o2 = d2 * rs * gamma[lane + 32] + beta[lane + 32];
    hout[n * 64 + lane] = fmaxf(o1, 0.f);
    hout[n * 64 + lane + 32] = fmaxf(o2, 0.f);
}

// ---------------- zero scratch (float4 stores) ----------------
__global__ __launch_bounds__(256)
void zero_k(float4* p, int n4)
{
    int i = blockIdx.x * 256 + threadIdx.x;
    if (i < n4) p[i] = make_float4(0.f, 0.f, 0.f, 0.f);
}

// ---------------- launch ----------------
extern "C" void kernel_launch(void* const* d_in, const int* in_sizes, int n_in,
                              void* d_out, int out_size)
{
    const float* x      = (const float*)d_in[0];
    const int*   ei     = (const int*)  d_in[1];
    const int*   et     = (const int*)  d_in[2];
    const float* W_in   = (const float*)d_in[3];
    const float* b_in   = (const float*)d_in[4];
    const float* W_rel  = (const float*)d_in[5];
    const float* W_gate = (const float*)d_in[6];
    const float* b_gate = (const float*)d_in[7];
    const float* W_att  = (const float*)d_in[8];
    const float* b_att  = (const float*)d_in[9];
    const float* ln_g   = (const float*)d_in[10];
    const float* ln_b   = (const float*)d_in[11];
    const float* W_out  = (const float*)d_in[12];
    const float* b_out  = (const float*)d_in[13];
    float* out = (float*)d_out;

    float *hbuf, *hWrp, *gatep, *aggp;
    cudaGetSymbolAddress((void**)&hbuf,  g_h);
    cudaGetSymbolAddress((void**)&hWrp,  g_hWr);
    cudaGetSymbolAddress((void**)&gatep, g_gate);
    cudaGetSymbolAddress((void**)&aggp,  g_agg);
    float* h0p = hbuf;
    float* h1p = hbuf + (size_t)NN * HH;

    cudaFuncSetAttribute(gemm64k, cudaFuncAttributeMaxDynamicSharedMemorySize, GEMM_SMEM);

    // zero agg once per launch (combine_k keeps it zeroed thereafter)
    int n4 = NN * 512 / 4;
    zero_k<<<(n4 + 255) / 256, 256>>>((float4*)aggp, n4);

    // input projection: h0 = relu(x @ W_in^T + b_in)
    gemm64k<<<dim3((NN + 127) / 128, 1), 128, GEMM_SMEM>>>(x, W_in, b_in, h0p, NN, 64, 1);

    float* hc = h0p;
    float* hn = h1p;
    for (int layer = 0; layer < LL; layer++) {
        gemm64k<<<dim3((NN + 127) / 128, 8), 128, GEMM_SMEM>>>(hc, W_rel,  nullptr, hWrp,  NN, 512, 0);
        gemm64k<<<dim3((NN + 127) / 128, 8), 128, GEMM_SMEM>>>(hc, W_gate, nullptr, gatep, NN, 512, 0);
        attproj_k<<<(NN + 15) / 16, 256>>>(hc, W_att);
        scores_k<<<(EE + 255) / 256, 256>>>(ei, et, b_att);
        expk_k<<<(EE + 255) / 256, 256>>>(et);
        scatter_k<<<(EE * 8 + 255) / 256, 256>>>(ei, et);
        combine_k<<<(NN + 7) / 8, 256>>>(hc, hn, b_gate, ln_g + layer * 64, ln_b + layer * 64);
        float* tmp = hc; hc = hn; hn = tmp;
    }

    // output projection: out = h @ W_out^T + b_out
    gemm64k<<<dim3((NN + 127) / 128, 1), 128, GEMM_SMEM>>>(hc, W_out, b_out, out, NN, 64, 0);
}

// round 2
// speedup vs baseline: 2.0033x; 2.0033x over previous
#include <cuda_runtime.h>

// ---------------- problem constants ----------------
#define NN 50000
#define EE 800000
#define HH 64
#define RR 8
#define LL 3
#define LN_EPS 1e-5f
#define NEG_SLOPE 0.2f

// ---------------- device scratch ----------------
__device__ float g_h[2 * NN * HH];        // ping-pong node features
__device__ float g_hWr[(size_t)NN * 512]; // h @ W_rel^T  [N][R*H]
__device__ float g_gate[(size_t)NN * 512];// raw gate pre-activation [N][R*H]
__device__ float g_ap[NN * 16];           // attention projections [N][16]
__device__ float g_sc[EE];                // per-edge scores
__device__ float g_ex[EE];                // per-edge exp(score - max)
__device__ unsigned g_menc[RR];           // per-type max (order-encoded)
__device__ float g_denom[RR];             // per-type softmax denominator
// CSR over dst (built once per launch)
__device__ int g_deg[NN];
__device__ int g_off[NN + 1];
__device__ int g_pos[NN];
__device__ int g_csrc[EE];                // (src<<3)|et in CSR order
__device__ int g_ceid[EE];                // original edge id in CSR order

__device__ __forceinline__ unsigned fenc(float f) {
    unsigned u = __float_as_uint(f);
    return (u & 0x80000000u) ? ~u : (u | 0x80000000u);
}
__device__ __forceinline__ float fdec(unsigned e) {
    unsigned u = (e & 0x80000000u) ? (e ^ 0x80000000u) : ~e;
    return __uint_as_float(u);
}

// ---------------- K=64 SGEMM: C[M,ncols] = act(A[M,64] @ B[ncols,64]^T + bias) ----
// BM=128, BN=64. 8x8 micro-tiles, packed fma.rn.f32x2, all-LDS.128 smem layout.
#define AS_STR 132   // 528B row stride: 16B-aligned
#define BS_STR 72    // 288B row stride: 16B-aligned
#define GEMM_SMEM ((64 * AS_STR + 64 * BS_STR) * 4)

__global__ __launch_bounds__(128)
void gemm64k(const float* __restrict__ A, const float* __restrict__ B,
             const float* __restrict__ bias, float* __restrict__ C,
             int M, int ncols, int act)
{
    extern __shared__ float smem[];
    float (*As)[AS_STR] = reinterpret_cast<float (*)[AS_STR]>(smem);
    float (*Bs)[BS_STR] = reinterpret_cast<float (*)[BS_STR]>(smem + 64 * AS_STR);

    const int tid = threadIdx.x;
    const int rowBase = blockIdx.x * 128;
    const int colBase = blockIdx.y * 64;

    #pragma unroll
    for (int i = 0; i < 16; i++) {
        int f = tid + i * 128;
        int r = f >> 4;
        int kq = (f & 15) << 2;
        int gr = rowBase + r;
        float4 v = make_float4(0.f, 0.f, 0.f, 0.f);
        if (gr < M) v = *reinterpret_cast<const float4*>(A + (size_t)gr * 64 + kq);
        As[kq + 0][r] = v.x; As[kq + 1][r] = v.y; As[kq + 2][r] = v.z; As[kq + 3][r] = v.w;
    }
    #pragma unroll
    for (int i = 0; i < 8; i++) {
        int f = tid + i * 128;
        int j = f >> 4;
        int kq = (f & 15) << 2;
        float4 v = *reinterpret_cast<const float4*>(B + (size_t)(colBase + j) * 64 + kq);
        Bs[kq + 0][j] = v.x; Bs[kq + 1][j] = v.y; Bs[kq + 2][j] = v.z; Bs[kq + 3][j] = v.w;
    }
    __syncthreads();

    const int tx = tid & 7;
    const int ty = tid >> 3;

    unsigned long long acc[8][4];
    #pragma unroll
    for (int i = 0; i < 8; i++)
        #pragma unroll
        for (int j = 0; j < 4; j++) acc[i][j] = 0ULL;

    #pragma unroll
    for (int k = 0; k < 64; k++) {
        const float4* ap = reinterpret_cast<const float4*>(&As[k][ty * 8]);
        float4 a03 = ap[0], a47 = ap[1];
        float a[8] = {a03.x, a03.y, a03.z, a03.w, a47.x, a47.y, a47.z, a47.w};
        const ulonglong2* bp = reinterpret_cast<const ulonglong2*>(&Bs[k][tx * 8]);
        ulonglong2 bb0 = bp[0], bb1 = bp[1];
        unsigned long long b2[4] = {bb0.x, bb0.y, bb1.x, bb1.y};
        #pragma unroll
        for (int i = 0; i < 8; i++) {
            unsigned long long a2;
            asm("mov.b64 %0, {%1, %1};" : "=l"(a2) : "f"(a[i]));
            #pragma unroll
            for (int j = 0; j < 4; j++)
                asm("fma.rn.f32x2 %0, %1, %2, %0;" : "+l"(acc[i][j]) : "l"(a2), "l"(b2[j]));
        }
    }

    #pragma unroll
    for (int i = 0; i < 8; i++) {
        int gr = rowBase + ty * 8 + i;
        if (gr >= M) continue;
        #pragma unroll
        for (int j = 0; j < 4; j++) {
            float lo, hi;
            asm("mov.b64 {%0, %1}, %2;" : "=f"(lo), "=f"(hi) : "l"(acc[i][j]));
            int col = colBase + tx * 8 + 2 * j;
            if (bias) { lo += bias[col]; hi += bias[col + 1]; }
            if (act == 1) { lo = fmaxf(lo, 0.f); hi = fmaxf(hi, 0.f); }
            *reinterpret_cast<float2*>(C + (size_t)gr * ncols + col) = make_float2(lo, hi);
        }
    }
}

// ---------------- CSR build ----------------
__global__ __launch_bounds__(256)
void zerodeg_k()
{
    int i = blockIdx.x * 256 + threadIdx.x;
    if (i < NN) g_deg[i] = 0;
}

__global__ __launch_bounds__(256)
void hist_k(const int* __restrict__ ei)
{
    int e = blockIdx.x * 256 + threadIdx.x;
    if (e < EE) atomicAdd(&g_deg[ei[EE + e]], 1);
}

__global__ __launch_bounds__(1024)
void scan_k()
{
    __shared__ int s[1024];
    __shared__ int carry_s;
    int tid = threadIdx.x;
    if (tid == 0) carry_s = 0;
    __syncthreads();
    for (int base = 0; base < NN; base += 4096) {
        int i0 = base + tid * 4;
        int v0 = (i0 + 0 < NN) ? g_deg[i0 + 0] : 0;
        int v1 = (i0 + 1 < NN) ? g_deg[i0 + 1] : 0;
        int v2 = (i0 + 2 < NN) ? g_deg[i0 + 2] : 0;
        int v3 = (i0 + 3 < NN) ? g_deg[i0 + 3] : 0;
        int tsum = v0 + v1 + v2 + v3;
        int val = tsum;
        s[tid] = val;
        __syncthreads();
        #pragma unroll
        for (int off = 1; off < 1024; off <<= 1) {
            int t = (tid >= off) ? s[tid - off] : 0;
            __syncthreads();
            val += t;
            s[tid] = val;
            __syncthreads();
        }
        int carry = carry_s;
        int o0 = carry + val - tsum;
        int o1 = o0 + v0, o2 = o1 + v1, o3 = o2 + v2;
        if (i0 + 0 < NN) { g_off[i0 + 0] = o0; g_pos[i0 + 0] = o0; }
        if (i0 + 1 < NN) { g_off[i0 + 1] = o1; g_pos[i0 + 1] = o1; }
        if (i0 + 2 < NN) { g_off[i0 + 2] = o2; g_pos[i0 + 2] = o2; }
        if (i0 + 3 < NN) { g_off[i0 + 3] = o3; g_pos[i0 + 3] = o3; }
        __syncthreads();
        if (tid == 1023) carry_s = carry + val;
        __syncthreads();
    }
    if (tid == 0) g_off[NN] = EE;
}

__global__ __launch_bounds__(256)
void fill_k(const int* __restrict__ ei, const int* __restrict__ et)
{
    int e = blockIdx.x * 256 + threadIdx.x;
    if (e >= EE) return;
    int dst = ei[EE + e];
    int p = atomicAdd(&g_pos[dst], 1);
    g_csrc[p] = (ei[e] << 3) | et[e];
    g_ceid[p] = e;
}

// ---------------- attention projections ----------------
__global__ __launch_bounds__(256)
void attproj_k(const float* __restrict__ h, const float* __restrict__ W_att)
{
    __shared__ float hs[16][65];
    __shared__ float ws[16][65];
    int tid = threadIdx.x;
    int nodeBase = blockIdx.x * 16;
    for (int i = tid; i < 16 * 64; i += 256) {
        int o = i >> 6, c = i & 63;
        ws[o][c] = W_att[(o & 7) * 128 + ((o >> 3) << 6) + c];
        int n = nodeBase + o;
        hs[o][c] = (n < NN) ? h[n * 64 + c] : 0.f;
    }
    __syncthreads();
    int nd = tid >> 4, o = tid & 15;
    float s = 0.f;
    #pragma unroll
    for (int c = 0; c < 64; c++) s += hs[nd][c] * ws[o][c];
    int n = nodeBase + nd;
    if (n < NN) g_ap[n * 16 + o] = s;
    if (blockIdx.x == 0 && tid < RR) { g_menc[tid] = 0u; g_denom[tid] = 0.f; }
}

// ---------------- per-edge scores + per-type max ----------------
__global__ __launch_bounds__(256)
void scores_k(const int* __restrict__ ei, const int* __restrict__ et,
              const float* __restrict__ b_att)
{
    __shared__ unsigned smax[RR];
    int tid = threadIdx.x;
    if (tid < RR) smax[tid] = 0u;
    __syncthreads();
    int e = blockIdx.x * 256 + tid;
    if (e < EE) {
        int t = et[e];
        int s = ei[e], d = ei[EE + e];
        float sc = g_ap[s * 16 + t] + g_ap[d * 16 + 8 + t] + b_att[t];
        sc = (sc > 0.f) ? sc : NEG_SLOPE * sc;
        g_sc[e] = sc;
        atomicMax(&smax[t], fenc(sc));
    }
    __syncthreads();
    if (tid < RR) atomicMax(&g_menc[tid], smax[tid]);
}

// ---------------- exp(score - max) + per-type denominator ----------------
__global__ __launch_bounds__(256)
void expk_k(const int* __restrict__ et)
{
    __shared__ float ssum[RR];
    int tid = threadIdx.x;
    if (tid < RR) ssum[tid] = 0.f;
    __syncthreads();
    int e = blockIdx.x * 256 + tid;
    if (e < EE) {
        int t = et[e];
        float m = fdec(g_menc[t]);
        float ex = __expf(g_sc[e] - m);
        g_ex[e] = ex;
        atomicAdd(&ssum[t], ex);
    }
    __syncthreads();
    if (tid < RR) atomicAdd(&g_denom[tid], ssum[tid]);
}

// ---------------- fused aggregate + gate + mean + residual + LN + relu ----------
// warp per node; register accumulators acc[8] (float2 per lane, cols 2*lane, 2*lane+1)
__global__ __launch_bounds__(256)
void aggcomb_k(const float* __restrict__ hin, float* __restrict__ hout,
               const float* __restrict__ b_gate,
               const float* __restrict__ gamma, const float* __restrict__ beta)
{
    __shared__ float sden[RR];
    int tid = threadIdx.x;
    if (tid < RR) sden[tid] = 1.f / g_denom[tid];
    __syncthreads();

    int warp = tid >> 5, lane = tid & 31;
    int n = blockIdx.x * 8 + warp;
    if (n >= NN) return;

    float2 acc[8];
    #pragma unroll
    for (int r = 0; r < 8; r++) acc[r] = make_float2(0.f, 0.f);

    int beg = g_off[n], end = g_off[n + 1];
    for (int b = beg; b < end; b += 32) {
        int j = b + lane;
        int packed = 0; float att = 0.f;
        if (j < end) {
            packed = g_csrc[j];
            int eid = g_ceid[j];
            att = g_ex[eid] * sden[packed & 7];
        }
        int cnt = min(32, end - b);
        // 2-deep pipeline: issue LDG for edge t before consuming edge t-1
        int pk_p = 0; float a_p = 0.f; float2 v_p = make_float2(0.f, 0.f);
        bool have = false;
        for (int t = 0; t < cnt; t++) {
            int pk = __shfl_sync(0xffffffffu, packed, t);
            float a = __shfl_sync(0xffffffffu, att, t);
            int src = pk >> 3, ety = pk & 7;
            float2 v = *reinterpret_cast<const float2*>(
                &g_hWr[(size_t)src * 512 + ety * 64 + lane * 2]);
            if (have) {
                int er = pk_p & 7;
                #pragma unroll
                for (int r = 0; r < 8; r++)
                    if (er == r) { acc[r].x += a_p * v_p.x; acc[r].y += a_p * v_p.y; }
            }
            pk_p = pk; a_p = a; v_p = v; have = true;
        }
        if (have) {
            int er = pk_p & 7;
            #pragma unroll
            for (int r = 0; r < 8; r++)
                if (er == r) { acc[r].x += a_p * v_p.x; acc[r].y += a_p * v_p.y; }
        }
    }

    // gate * agg, mean over r
    size_t base = (size_t)n * 512;
    float hx = 0.f, hy = 0.f;
    #pragma unroll
    for (int r = 0; r < 8; r++) {
        int o = r * 64 + lane * 2;
        float2 gp = *reinterpret_cast<const float2*>(&g_gate[base + o]);
        float2 bg = *reinterpret_cast<const float2*>(&b_gate[o]);
        float sx = 1.f / (1.f + __expf(-(gp.x + bg.x)));
        float sy = 1.f / (1.f + __expf(-(gp.y + bg.y)));
        hx += sx * acc[r].x;
        hy += sy * acc[r].y;
    }
    float2 hv = *reinterpret_cast<const float2*>(&hin[n * 64 + lane * 2]);
    float h1 = hv.x + hx * 0.125f;
    float h2 = hv.y + hy * 0.125f;

    // LayerNorm over 64 cols (2 per lane)
    float s = h1 + h2;
    #pragma unroll
    for (int o = 16; o > 0; o >>= 1) s += __shfl_xor_sync(0xffffffffu, s, o);
    float mu = s * (1.f / 64.f);
    float d1 = h1 - mu, d2 = h2 - mu;
    float v = d1 * d1 + d2 * d2;
    #pragma unroll
    for (int o = 16; o > 0; o >>= 1) v += __shfl_xor_sync(0xffffffffu, v, o);
    float rs = rsqrtf(v * (1.f / 64.f) + LN_EPS);
    float o1 = d1 * rs * gamma[lane * 2] + beta[lane * 2];
    float o2 = d2 * rs * gamma[lane * 2 + 1] + beta[lane * 2 + 1];
    *reinterpret_cast<float2*>(&hout[n * 64 + lane * 2]) =
        make_float2(fmaxf(o1, 0.f), fmaxf(o2, 0.f));
}

// ---------------- launch ----------------
extern "C" void kernel_launch(void* const* d_in, const int* in_sizes, int n_in,
                              void* d_out, int out_size)
{
    const float* x      = (const float*)d_in[0];
    const int*   ei     = (const int*)  d_in[1];
    const int*   et     = (const int*)  d_in[2];
    const float* W_in   = (const float*)d_in[3];
    const float* b_in   = (const float*)d_in[4];
    const float* W_rel  = (const float*)d_in[5];
    const float* W_gate = (const float*)d_in[6];
    const float* b_gate = (const float*)d_in[7];
    const float* W_att  = (const float*)d_in[8];
    const float* b_att  = (const float*)d_in[9];
    const float* ln_g   = (const float*)d_in[10];
    const float* ln_b   = (const float*)d_in[11];
    const float* W_out  = (const float*)d_in[12];
    const float* b_out  = (const float*)d_in[13];
    float* out = (float*)d_out;

    float *hbuf, *hWrp, *gatep;
    cudaGetSymbolAddress((void**)&hbuf,  g_h);
    cudaGetSymbolAddress((void**)&hWrp,  g_hWr);
    cudaGetSymbolAddress((void**)&gatep, g_gate);
    float* h0p = hbuf;
    float* h1p = hbuf + (size_t)NN * HH;

    cudaFuncSetAttribute(gemm64k, cudaFuncAttributeMaxDynamicSharedMemorySize, GEMM_SMEM);

    // ---- CSR over dst (built once; reused for all 3 layers) ----
    zerodeg_k<<<(NN + 255) / 256, 256>>>();
    hist_k<<<(EE + 255) / 256, 256>>>(ei);
    scan_k<<<1, 1024>>>();
    fill_k<<<(EE + 255) / 256, 256>>>(ei, et);

    // input projection
    gemm64k<<<dim3((NN + 127) / 128, 1), 128, GEMM_SMEM>>>(x, W_in, b_in, h0p, NN, 64, 1);

    float* hc = h0p;
    float* hn = h1p;
    for (int layer = 0; layer < LL; layer++) {
        gemm64k<<<dim3((NN + 127) / 128, 8), 128, GEMM_SMEM>>>(hc, W_rel,  nullptr, hWrp,  NN, 512, 0);
        gemm64k<<<dim3((NN + 127) / 128, 8), 128, GEMM_SMEM>>>(hc, W_gate, nullptr, gatep, NN, 512, 0);
        attproj_k<<<(NN + 15) / 16, 256>>>(hc, W_att);
        scores_k<<<(EE + 255) / 256, 256>>>(ei, et, b_att);
        expk_k<<<(EE + 255) / 256, 256>>>(et);
        aggcomb_k<<<(NN + 7) / 8, 256>>>(hc, hn, b_gate, ln_g + layer * 64, ln_b + layer * 64);
        float* tmp = hc; hc = hn; hn = tmp;
    }

    gemm64k<<<dim3((NN + 127) / 128, 1), 128, GEMM_SMEM>>>(hc, W_out, b_out, out, NN, 64, 0);
}

// round 3
// speedup vs baseline: 2.1265x; 1.0615x over previous
#include <cuda_runtime.h>

// ---------------- problem constants ----------------
#define NN 50000
#define EE 800000
#define HH 64
#define RR 8
#define LL 3
#define LN_EPS 1e-5f
#define NEG_SLOPE 0.2f

// ---------------- device scratch ----------------
__device__ float g_h[2 * NN * HH];         // ping-pong node features
__device__ float g_prod[(size_t)NN * 512]; // relgemm output (spre @ W_rel)
__device__ float g_gate[(size_t)NN * 512]; // raw gate pre-activation
__device__ float g_spre[(size_t)NN * 512]; // att-weighted h sums per (n,r)
__device__ float g_ap[NN * 16];            // attention projections [N][16]
__device__ float g_sc[EE];                 // per-edge scores (orig order)
__device__ float g_exc[EE];                // exp(score-max) in CSR order
__device__ unsigned g_menc[RR];
__device__ float g_denom[RR];
// CSR over dst
__device__ int g_deg[NN];
__device__ int g_off[NN + 1];
__device__ int g_pos[NN];
__device__ int g_csrc[EE];                 // (src<<3)|et in CSR order
__device__ int g_e2c[EE];                  // edge id -> CSR slot

__device__ __forceinline__ unsigned fenc(float f) {
    unsigned u = __float_as_uint(f);
    return (u & 0x80000000u) ? ~u : (u | 0x80000000u);
}
__device__ __forceinline__ float fdec(unsigned e) {
    unsigned u = (e & 0x80000000u) ? (e ^ 0x80000000u) : ~e;
    return __uint_as_float(u);
}

// ---------------- K=64 SGEMM ----------------
// C[gr, colBase+c] = act(A[gr, aoff+k] dot Brow + bias)
// batched=0: B rows indexed by absolute col (colBase+j), aoff=0
// batched=1: per-y 64x64 weight slice (B + colBase*64), A k-slice at aoff=colBase
#define AS_STR 132
#define BS_STR 72
#define GEMM_SMEM ((64 * AS_STR + 64 * BS_STR) * 4)

__global__ __launch_bounds__(128)
void gemm64k(const float* __restrict__ A, int lda,
             const float* __restrict__ B,
             const float* __restrict__ bias, float* __restrict__ C, int ldc,
             int M, int batched, int act)
{
    extern __shared__ float smem[];
    float (*As)[AS_STR] = reinterpret_cast<float (*)[AS_STR]>(smem);
    float (*Bs)[BS_STR] = reinterpret_cast<float (*)[BS_STR]>(smem + 64 * AS_STR);

    const int tid = threadIdx.x;
    const int rowBase = blockIdx.x * 128;
    const int colBase = blockIdx.y * 64;
    const int aoff = batched ? colBase : 0;

    #pragma unroll
    for (int i = 0; i < 16; i++) {
        int f = tid + i * 128;
        int r = f >> 4;
        int kq = (f & 15) << 2;
        int gr = rowBase + r;
        float4 v = make_float4(0.f, 0.f, 0.f, 0.f);
        if (gr < M) v = *reinterpret_cast<const float4*>(A + (size_t)gr * lda + aoff + kq);
        As[kq + 0][r] = v.x; As[kq + 1][r] = v.y; As[kq + 2][r] = v.z; As[kq + 3][r] = v.w;
    }
    #pragma unroll
    for (int i = 0; i < 8; i++) {
        int f = tid + i * 128;
        int j = f >> 4;
        int kq = (f & 15) << 2;
        const float* brow = batched ? (B + (size_t)colBase * 64 + j * 64)
                                    : (B + (size_t)(colBase + j) * 64);
        float4 v = *reinterpret_cast<const float4*>(brow + kq);
        Bs[kq + 0][j] = v.x; Bs[kq + 1][j] = v.y; Bs[kq + 2][j] = v.z; Bs[kq + 3][j] = v.w;
    }
    __syncthreads();

    const int tx = tid & 7;
    const int ty = tid >> 3;

    unsigned long long acc[8][4];
    #pragma unroll
    for (int i = 0; i < 8; i++)
        #pragma unroll
        for (int j = 0; j < 4; j++) acc[i][j] = 0ULL;

    #pragma unroll
    for (int k = 0; k < 64; k++) {
        const float4* ap = reinterpret_cast<const float4*>(&As[k][ty * 8]);
        float4 a03 = ap[0], a47 = ap[1];
        float a[8] = {a03.x, a03.y, a03.z, a03.w, a47.x, a47.y, a47.z, a47.w};
        const ulonglong2* bp = reinterpret_cast<const ulonglong2*>(&Bs[k][tx * 8]);
        ulonglong2 bb0 = bp[0], bb1 = bp[1];
        unsigned long long b2[4] = {bb0.x, bb0.y, bb1.x, bb1.y};
        #pragma unroll
        for (int i = 0; i < 8; i++) {
            unsigned long long a2;
            asm("mov.b64 %0, {%1, %1};" : "=l"(a2) : "f"(a[i]));
            #pragma unroll
            for (int j = 0; j < 4; j++)
                asm("fma.rn.f32x2 %0, %1, %2, %0;" : "+l"(acc[i][j]) : "l"(a2), "l"(b2[j]));
        }
    }

    #pragma unroll
    for (int i = 0; i < 8; i++) {
        int gr = rowBase + ty * 8 + i;
        if (gr >= M) continue;
        #pragma unroll
        for (int j = 0; j < 4; j++) {
            float lo, hi;
            asm("mov.b64 {%0, %1}, %2;" : "=f"(lo), "=f"(hi) : "l"(acc[i][j]));
            int col = colBase + tx * 8 + 2 * j;
            if (bias) { lo += bias[col]; hi += bias[col + 1]; }
            if (act == 1) { lo = fmaxf(lo, 0.f); hi = fmaxf(hi, 0.f); }
            *reinterpret_cast<float2*>(C + (size_t)gr * ldc + col) = make_float2(lo, hi);
        }
    }
}

// ---------------- CSR build ----------------
__global__ __launch_bounds__(256)
void zerodeg_k()
{
    int i = blockIdx.x * 256 + threadIdx.x;
    if (i < NN) g_deg[i] = 0;
}

__global__ __launch_bounds__(256)
void hist_k(const int* __restrict__ ei)
{
    int e = blockIdx.x * 256 + threadIdx.x;
    if (e < EE) atomicAdd(&g_deg[ei[EE + e]], 1);
}

__global__ __launch_bounds__(1024)
void scan_k()
{
    __shared__ int s[1024];
    __shared__ int carry_s;
    int tid = threadIdx.x;
    if (tid == 0) carry_s = 0;
    __syncthreads();
    for (int base = 0; base < NN; base += 4096) {
        int i0 = base + tid * 4;
        int v0 = (i0 + 0 < NN) ? g_deg[i0 + 0] : 0;
        int v1 = (i0 + 1 < NN) ? g_deg[i0 + 1] : 0;
        int v2 = (i0 + 2 < NN) ? g_deg[i0 + 2] : 0;
        int v3 = (i0 + 3 < NN) ? g_deg[i0 + 3] : 0;
        int tsum = v0 + v1 + v2 + v3;
        int val = tsum;
        s[tid] = val;
        __syncthreads();
        #pragma unroll
        for (int off = 1; off < 1024; off <<= 1) {
            int t = (tid >= off) ? s[tid - off] : 0;
            __syncthreads();
            val += t;
            s[tid] = val;
            __syncthreads();
        }
        int carry = carry_s;
        int o0 = carry + val - tsum;
        int o1 = o0 + v0, o2 = o1 + v1, o3 = o2 + v2;
        if (i0 + 0 < NN) { g_off[i0 + 0] = o0; g_pos[i0 + 0] = o0; }
        if (i0 + 1 < NN) { g_off[i0 + 1] = o1; g_pos[i0 + 1] = o1; }
        if (i0 + 2 < NN) { g_off[i0 + 2] = o2; g_pos[i0 + 2] = o2; }
        if (i0 + 3 < NN) { g_off[i0 + 3] = o3; g_pos[i0 + 3] = o3; }
        __syncthreads();
        if (tid == 1023) carry_s = carry + val;
        __syncthreads();
    }
    if (tid == 0) g_off[NN] = EE;
}

__global__ __launch_bounds__(256)
void fill_k(const int* __restrict__ ei, const int* __restrict__ et)
{
    int e = blockIdx.x * 256 + threadIdx.x;
    if (e >= EE) return;
    int dst = ei[EE + e];
    int p = atomicAdd(&g_pos[dst], 1);
    g_csrc[p] = (ei[e] << 3) | et[e];
    g_e2c[e] = p;
}

// ---------------- attention projections ----------------
__global__ __launch_bounds__(256)
void attproj_k(const float* __restrict__ h, const float* __restrict__ W_att)
{
    __shared__ float hs[16][65];
    __shared__ float ws[16][65];
    int tid = threadIdx.x;
    int nodeBase = blockIdx.x * 16;
    for (int i = tid; i < 16 * 64; i += 256) {
        int o = i >> 6, c = i & 63;
        ws[o][c] = W_att[(o & 7) * 128 + ((o >> 3) << 6) + c];
        int n = nodeBase + o;
        hs[o][c] = (n < NN) ? h[n * 64 + c] : 0.f;
    }
    __syncthreads();
    int nd = tid >> 4, o = tid & 15;
    float s = 0.f;
    #pragma unroll
    for (int c = 0; c < 64; c++) s += hs[nd][c] * ws[o][c];
    int n = nodeBase + nd;
    if (n < NN) g_ap[n * 16 + o] = s;
    if (blockIdx.x == 0 && tid < RR) { g_menc[tid] = 0u; g_denom[tid] = 0.f; }
}

// ---------------- per-edge scores + per-type max ----------------
__global__ __launch_bounds__(256)
void scores_k(const int* __restrict__ ei, const int* __restrict__ et,
              const float* __restrict__ b_att)
{
    __shared__ unsigned smax[RR];
    int tid = threadIdx.x;
    if (tid < RR) smax[tid] = 0u;
    __syncthreads();
    int e = blockIdx.x * 256 + tid;
    if (e < EE) {
        int t = et[e];
        int s = ei[e], d = ei[EE + e];
        float sc = g_ap[s * 16 + t] + g_ap[d * 16 + 8 + t] + b_att[t];
        sc = (sc > 0.f) ? sc : NEG_SLOPE * sc;
        g_sc[e] = sc;
        atomicMax(&smax[t], fenc(sc));
    }
    __syncthreads();
    if (tid < RR) atomicMax(&g_menc[tid], smax[tid]);
}

// ---------------- exp(score - max), scattered into CSR order ----------------
__global__ __launch_bounds__(256)
void expk_k(const int* __restrict__ et)
{
    __shared__ float ssum[RR];
    int tid = threadIdx.x;
    if (tid < RR) ssum[tid] = 0.f;
    __syncthreads();
    int e = blockIdx.x * 256 + tid;
    if (e < EE) {
        int t = et[e];
        float m = fdec(g_menc[t]);
        float ex = __expf(g_sc[e] - m);
        g_exc[g_e2c[e]] = ex;
        atomicAdd(&ssum[t], ex);
    }
    __syncthreads();
    if (tid < RR) atomicAdd(&g_denom[tid], ssum[tid]);
}

// ---------------- aggregate att-weighted h[src] per (dst, r) ----------------
// warp per node; L2-resident h gather; uniform broadcast CSR reads; unroll 4.
__global__ __launch_bounds__(256)
void aggscatter_k(const float* __restrict__ h)
{
    __shared__ float sden[RR];
    int tid = threadIdx.x;
    if (tid < RR) sden[tid] = 1.f / g_denom[tid];
    __syncthreads();

    int warp = tid >> 5, lane = tid & 31;
    int n = blockIdx.x * 8 + warp;
    if (n >= NN) return;

    float2 acc[8];
    #pragma unroll
    for (int r = 0; r < 8; r++) acc[r] = make_float2(0.f, 0.f);

    int beg = g_off[n], end = g_off[n + 1];
    for (int b = beg; b < end; b += 4) {
        int pk[4]; float at[4];
        #pragma unroll
        for (int i = 0; i < 4; i++) {
            int j = b + i;
            int jc = (j < end) ? j : beg;          // clamp keeps loads in-bounds
            pk[i] = g_csrc[jc];
            float ex = g_exc[jc];
            at[i] = (j < end) ? ex * sden[pk[i] & 7] : 0.f;
        }
        float2 v[4];
        #pragma unroll
        for (int i = 0; i < 4; i++)
            v[i] = *reinterpret_cast<const float2*>(&h[(pk[i] >> 3) * 64 + lane * 2]);
        #pragma unroll
        for (int i = 0; i < 4; i++) {
            int er = pk[i] & 7;
            #pragma unroll
            for (int r = 0; r < 8; r++)
                if (er == r) { acc[r].x += at[i] * v[i].x; acc[r].y += at[i] * v[i].y; }
        }
    }

    size_t base = (size_t)n * 512;
    #pragma unroll
    for (int r = 0; r < 8; r++)
        *reinterpret_cast<float2*>(&g_spre[base + r * 64 + lane * 2]) = acc[r];
}

// ---------------- gate*prod mean + residual + LN + relu ----------------
__global__ __launch_bounds__(256)
void combine_k(const float* __restrict__ hin, float* __restrict__ hout,
               const float* __restrict__ b_gate,
               const float* __restrict__ gamma, const float* __restrict__ beta)
{
    int tid = threadIdx.x;
    int warp = tid >> 5, lane = tid & 31;
    int n = blockIdx.x * 8 + warp;
    if (n >= NN) return;

    size_t base = (size_t)n * 512;
    float hx = 0.f, hy = 0.f;
    #pragma unroll
    for (int r = 0; r < 8; r++) {
        int o = r * 64 + lane * 2;
        float2 gp = *reinterpret_cast<const float2*>(&g_gate[base + o]);
        float2 pv = *reinterpret_cast<const float2*>(&g_prod[base + o]);
        float2 bg = *reinterpret_cast<const float2*>(&b_gate[o]);
        float sx = 1.f / (1.f + __expf(-(gp.x + bg.x)));
        float sy = 1.f / (1.f + __expf(-(gp.y + bg.y)));
        hx += sx * pv.x;
        hy += sy * pv.y;
    }
    float2 hv = *reinterpret_cast<const float2*>(&hin[n * 64 + lane * 2]);
    float h1 = hv.x + hx * 0.125f;
    float h2 = hv.y + hy * 0.125f;

    float s = h1 + h2;
    #pragma unroll
    for (int o = 16; o > 0; o >>= 1) s += __shfl_xor_sync(0xffffffffu, s, o);
    float mu = s * (1.f / 64.f);
    float d1 = h1 - mu, d2 = h2 - mu;
    float v = d1 * d1 + d2 * d2;
    #pragma unroll
    for (int o = 16; o > 0; o >>= 1) v += __shfl_xor_sync(0xffffffffu, v, o);
    float rs = rsqrtf(v * (1.f / 64.f) + LN_EPS);
    float o1 = d1 * rs * gamma[lane * 2] + beta[lane * 2];
    float o2 = d2 * rs * gamma[lane * 2 + 1] + beta[lane * 2 + 1];
    *reinterpret_cast<float2*>(&hout[n * 64 + lane * 2]) =
        make_float2(fmaxf(o1, 0.f), fmaxf(o2, 0.f));
}

// ---------------- launch ----------------
extern "C" void kernel_launch(void* const* d_in, const int* in_sizes, int n_in,
                              void* d_out, int out_size)
{
    const float* x      = (const float*)d_in[0];
    const int*   ei     = (const int*)  d_in[1];
    const int*   et     = (const int*)  d_in[2];
    const float* W_in   = (const float*)d_in[3];
    const float* b_in   = (const float*)d_in[4];
    const float* W_rel  = (const float*)d_in[5];
    const float* W_gate = (const float*)d_in[6];
    const float* b_gate = (const float*)d_in[7];
    const float* W_att  = (const float*)d_in[8];
    const float* b_att  = (const float*)d_in[9];
    const float* ln_g   = (const float*)d_in[10];
    const float* ln_b   = (const float*)d_in[11];
    const float* W_out  = (const float*)d_in[12];
    const float* b_out  = (const float*)d_in[13];
    float* out = (float*)d_out;

    float *hbuf, *sprep, *gatep, *prodp;
    cudaGetSymbolAddress((void**)&hbuf,  g_h);
    cudaGetSymbolAddress((void**)&sprep, g_spre);
    cudaGetSymbolAddress((void**)&gatep, g_gate);
    cudaGetSymbolAddress((void**)&prodp, g_prod);
    float* h0p = hbuf;
    float* h1p = hbuf + (size_t)NN * HH;

    cudaFuncSetAttribute(gemm64k, cudaFuncAttributeMaxDynamicSharedMemorySize, GEMM_SMEM);

    // CSR over dst (built once; reused for all layers)
    zerodeg_k<<<(NN + 255) / 256, 256>>>();
    hist_k<<<(EE + 255) / 256, 256>>>(ei);
    scan_k<<<1, 1024>>>();
    fill_k<<<(EE + 255) / 256, 256>>>(ei, et);

    // input projection: h0 = relu(x @ W_in^T + b_in)
    gemm64k<<<dim3((NN + 127) / 128, 1), 128, GEMM_SMEM>>>(x, 64, W_in, b_in, h0p, 64, NN, 0, 1);

    float* hc = h0p;
    float* hn = h1p;
    for (int layer = 0; layer < LL; layer++) {
        // gate preactivation: h @ W_gate^T  -> g_gate [N,512]
        gemm64k<<<dim3((NN + 127) / 128, 8), 128, GEMM_SMEM>>>(hc, 64, W_gate, nullptr, gatep, 512, NN, 0, 0);
        attproj_k<<<(NN + 15) / 16, 256>>>(hc, W_att);
        scores_k<<<(EE + 255) / 256, 256>>>(ei, et, b_att);
        expk_k<<<(EE + 255) / 256, 256>>>(et);
        // spre[n,r,:] = sum over in-edges att * h[src]
        aggscatter_k<<<(NN + 7) / 8, 256>>>(hc);
        // prod[n,r,:] = spre[n,r,:] @ W_rel[r]^T   (batched GEMM)
        gemm64k<<<dim3((NN + 127) / 128, 8), 128, GEMM_SMEM>>>(sprep, 512, W_rel, nullptr, prodp, 512, NN, 1, 0);
        combine_k<<<(NN + 7) / 8, 256>>>(hc, hn, b_gate, ln_g + layer * 64, ln_b + layer * 64);
        float* tmp = hc; hc = hn; hn = tmp;
    }

    gemm64k<<<dim3((NN + 127) / 128, 1), 128, GEMM_SMEM>>>(hc, 64, W_out, b_out, out, 64, NN, 0, 0);
}